// round 16
// baseline (speedup 1.0000x reference)
#include <cuda_runtime.h>
#include <cstdint>

#define NN 100000
#define NE 1600000
#define DH 64
#define SCAN_BLK 1024
#define NB ((NN + SCAN_BLK - 1) / SCAN_BLK) // 98
#define AS_STRIDE 68
#define WS_STRIDE 132

// ---------------- scratch (no allocations allowed) ----------------
__device__ float g_agg[(size_t)NN * DH];
__device__ float g_h1 [(size_t)NN * DH];
__device__ int   g_esrc[NE];              // BYTE offsets of src feature rows (src*256)
__device__ int   g_rank[NE];              // per-edge rank within its dst segment
__device__ int   g_cnt[NN];
__device__ int   g_offs[NN + 1];          // PARTIAL (per-scan-block) exclusive offsets
__device__ int   g_bsum[NB];              // exclusive block sums

__device__ __forceinline__ float to_tf32(float x) {
    unsigned u;
    asm("cvt.rna.tf32.f32 %0, %1;" : "=r"(u) : "f"(x));
    return __uint_as_float(u);
}

__device__ __forceinline__ void mma_tf32(float c[4], const unsigned a[4], const unsigned b[2]) {
    asm("mma.sync.aligned.m16n8k8.row.col.f32.tf32.tf32.f32 "
        "{%0,%1,%2,%3}, {%4,%5,%6,%7}, {%8,%9}, {%0,%1,%2,%3};"
        : "+f"(c[0]), "+f"(c[1]), "+f"(c[2]), "+f"(c[3])
        : "r"(a[0]), "r"(a[1]), "r"(a[2]), "r"(a[3]), "r"(b[0]), "r"(b[1]));
}

// per-block int64-vs-int32 detection (broadcast loads; negligible)
__device__ __forceinline__ int detect_is64_block(const void* ei) {
    __shared__ int s_is64;
    if (threadIdx.x == 0) {
        const long long* p = (const long long*)ei;
        bool all64 = true;
        #pragma unroll
        for (int j = 0; j < 8; ++j) {
            long long v = p[j];
            if (v < 0 || v >= NN) all64 = false;
        }
        s_is64 = all64 ? 1 : 0;
    }
    __syncthreads();
    return s_is64;
}

// ---------------- histogram + per-edge rank (4 edges/thread) ----------------
__global__ void hist_dst(const void* __restrict__ ei, int* __restrict__ cnt,
                         int* __restrict__ rank) {
    int is64 = detect_is64_block(ei);
    int i = (blockIdx.x * blockDim.x + threadIdx.x) * 4;
    if (i >= NE) return;
    int d0, d1, d2, d3;
    if (is64) {
        longlong4 q = *reinterpret_cast<const longlong4*>((const long long*)ei + NE + i);
        d0 = (int)q.x; d1 = (int)q.y; d2 = (int)q.z; d3 = (int)q.w;
    } else {
        int4 q = *reinterpret_cast<const int4*>((const int*)ei + NE + i);
        d0 = q.x; d1 = q.y; d2 = q.z; d3 = q.w;
    }
    int4 r;
    r.x = atomicAdd(&cnt[d0], 1);
    r.y = atomicAdd(&cnt[d1], 1);
    r.z = atomicAdd(&cnt[d2], 1);
    r.w = atomicAdd(&cnt[d3], 1);
    *reinterpret_cast<int4*>(rank + i) = r;
}

// ---------------- per-block exclusive scan (partial offs) ----------------
__global__ void scan_blocks(const int* __restrict__ cnt,
                            int* __restrict__ offs, int* __restrict__ bsum) {
    __shared__ int sh[256];
    int t = threadIdx.x;
    int base = blockIdx.x * SCAN_BLK + t * 4;
    int c0 = (base + 0 < NN) ? cnt[base + 0] : 0;
    int c1 = (base + 1 < NN) ? cnt[base + 1] : 0;
    int c2 = (base + 2 < NN) ? cnt[base + 2] : 0;
    int c3 = (base + 3 < NN) ? cnt[base + 3] : 0;
    int s = c0 + c1 + c2 + c3;
    sh[t] = s;
    __syncthreads();
    #pragma unroll
    for (int off = 1; off < 256; off <<= 1) {
        int v = (t >= off) ? sh[t - off] : 0;
        __syncthreads();
        sh[t] += v;
        __syncthreads();
    }
    int excl = sh[t] - s;
    if (t == 255) bsum[blockIdx.x] = sh[255];
    if (base + 0 < NN) offs[base + 0] = excl;  excl += c0;
    if (base + 1 < NN) offs[base + 1] = excl;  excl += c1;
    if (base + 2 < NN) offs[base + 2] = excl;  excl += c2;
    if (base + 3 < NN) offs[base + 3] = excl;
}

__global__ void scan_bsums(int* __restrict__ bsum, int* __restrict__ offs) {
    __shared__ int sh[128];
    int t = threadIdx.x;
    int v = (t < NB) ? bsum[t] : 0;
    sh[t] = v;
    __syncthreads();
    #pragma unroll
    for (int off = 1; off < 128; off <<= 1) {
        int u = (t >= off) ? sh[t - off] : 0;
        __syncthreads();
        sh[t] += u;
        __syncthreads();
    }
    if (t < NB) bsum[t] = sh[t] - v;           // exclusive
    if (t == NB - 1) offs[NN] = v;             // partial: offs[NN]+bsum[NB-1] = NE
}

// ---------------- place edges, NO atomics (rank trick) ----------------
__global__ void place_edges(const void* __restrict__ ei,
                            const int* __restrict__ rank,
                            const int* __restrict__ offs,
                            const int* __restrict__ bsum,
                            int* __restrict__ esrc) {
    int is64 = detect_is64_block(ei);
    int i = (blockIdx.x * blockDim.x + threadIdx.x) * 4;
    if (i >= NE) return;
    int s0, s1, s2, s3, d0, d1, d2, d3;
    if (is64) {
        const long long* p = (const long long*)ei;
        longlong4 qs = *reinterpret_cast<const longlong4*>(p + i);
        longlong4 qd = *reinterpret_cast<const longlong4*>(p + NE + i);
        s0 = (int)qs.x; s1 = (int)qs.y; s2 = (int)qs.z; s3 = (int)qs.w;
        d0 = (int)qd.x; d1 = (int)qd.y; d2 = (int)qd.z; d3 = (int)qd.w;
    } else {
        const int* p = (const int*)ei;
        int4 qs = *reinterpret_cast<const int4*>(p + i);
        int4 qd = *reinterpret_cast<const int4*>(p + NE + i);
        s0 = qs.x; s1 = qs.y; s2 = qs.z; s3 = qs.w;
        d0 = qd.x; d1 = qd.y; d2 = qd.z; d3 = qd.w;
    }
    int4 r = *reinterpret_cast<const int4*>(rank + i);
    esrc[offs[d0] + bsum[d0 >> 10] + r.x] = s0 << 8;   // byte offsets (row = 256B)
    esrc[offs[d1] + bsum[d1 >> 10] + r.y] = s1 << 8;
    esrc[offs[d2] + bsum[d2 >> 10] + r.z] = s2 << 8;
    esrc[offs[d3] + bsum[d3 >> 10] + r.w] = s3 << 8;
}

// ---------------- gather: float4/lane, byte offsets, esrc-prefetch ----------
__global__ void __launch_bounds__(256)
gather_agg(const float* __restrict__ feat,    // rows of 256B
           const int* __restrict__ offs,      // partial
           const int* __restrict__ bsum,
           const int* __restrict__ esrc,      // byte offsets
           float4* __restrict__ agg) {        // [NN*16]
    int node = blockIdx.x * (blockDim.x >> 5) + (threadIdx.x >> 5);
    if (node >= NN) return;
    int lane = threadIdx.x & 31;
    int half = lane >> 4;
    int sub  = lane & 15;
    int s0 = offs[node]     + bsum[node >> 10];
    int s1 = offs[node + 1] + bsum[(node + 1) >> 10];
    const char* fb = reinterpret_cast<const char*>(feat) + sub * 16;
    float ax = 0.f, ay = 0.f, az = 0.f, aw = 0.f;
    int j = s0;

    if (j + 8 <= s1) {
        int e0 = esrc[j + half];
        int e1 = esrc[j + 2 + half];
        int e2 = esrc[j + 4 + half];
        int e3 = esrc[j + 6 + half];
        for (;;) {
            bool more = (j + 16 <= s1);
            int n0, n1, n2, n3;
            if (more) {
                n0 = esrc[j + 8 + half];
                n1 = esrc[j + 10 + half];
                n2 = esrc[j + 12 + half];
                n3 = esrc[j + 14 + half];
            }
            float4 v0 = *reinterpret_cast<const float4*>(fb + e0);
            float4 v1 = *reinterpret_cast<const float4*>(fb + e1);
            float4 v2 = *reinterpret_cast<const float4*>(fb + e2);
            float4 v3 = *reinterpret_cast<const float4*>(fb + e3);
            ax += (v0.x + v1.x) + (v2.x + v3.x);
            ay += (v0.y + v1.y) + (v2.y + v3.y);
            az += (v0.z + v1.z) + (v2.z + v3.z);
            aw += (v0.w + v1.w) + (v2.w + v3.w);
            j += 8;
            if (!more) break;
            e0 = n0; e1 = n1; e2 = n2; e3 = n3;
        }
    }
    for (; j + 4 <= s1; j += 4) {
        int e0 = esrc[j + half];
        int e1 = esrc[j + 2 + half];
        float4 v0 = *reinterpret_cast<const float4*>(fb + e0);
        float4 v1 = *reinterpret_cast<const float4*>(fb + e1);
        ax += v0.x + v1.x;  ay += v0.y + v1.y;
        az += v0.z + v1.z;  aw += v0.w + v1.w;
    }
    for (; j + 2 <= s1; j += 2) {
        int e = esrc[j + half];
        float4 v = *reinterpret_cast<const float4*>(fb + e);
        ax += v.x;  ay += v.y;  az += v.z;  aw += v.w;
    }
    if (j < s1 && half == 0) {
        float4 v = *reinterpret_cast<const float4*>(fb + esrc[j]);
        ax += v.x;  ay += v.y;  az += v.z;  aw += v.w;
    }
    ax += __shfl_xor_sync(0xffffffffu, ax, 16);
    ay += __shfl_xor_sync(0xffffffffu, ay, 16);
    az += __shfl_xor_sync(0xffffffffu, az, 16);
    aw += __shfl_xor_sync(0xffffffffu, aw, 16);
    if (half == 0) agg[(size_t)node * 16 + sub] = make_float4(ax, ay, az, aw);
}

// ---------------- tf32 tensor-core dual-GEMM (+ fused head on FINAL) ----------
// Stages Wrel/Wroot directly from global (tf32-rounded on the fly) — no prep kernel.
template<bool FINAL>
__global__ void __launch_bounds__(256)
gemm_tc(const float* __restrict__ A0,    // agg [NN,64]
        const float* __restrict__ A1,    // xin [NN,64]
        const float* __restrict__ Wrel,  // [64,64] row-major
        const float* __restrict__ Wroot, // [64,64] row-major
        const float* __restrict__ bias,  // [64]
        const float* __restrict__ Wlin,  // [3,64]  (FINAL)
        const float* __restrict__ blin,  // [3]     (FINAL)
        float* __restrict__ out) {       // [NN,64] or [NN,3]
    extern __shared__ float sm[];
    float* Bs = sm;                         // [64][132]
    float* As = Bs + 64 * WS_STRIDE;        // [128][68]
    float* bs = As + 128 * AS_STRIDE;       // [64]
    float* Wl = bs + 64;                    // [192]

    const int tid    = threadIdx.x;
    const int lane   = tid & 31;
    const int warp   = tid >> 5;
    const int warp_m = warp & 3;
    const int warp_n = warp >> 2;
    const int gid    = lane >> 2;
    const int tig    = lane & 3;
    const int m0     = blockIdx.x * 128;

    // stage weights: Bs[n][k] = k<64 ? Wrel[n][k] : (k<128 ? Wroot[n][k-64] : 0)
    for (int i = tid; i < 64 * WS_STRIDE; i += 256) {
        int n = i / WS_STRIDE;
        int k = i - n * WS_STRIDE;
        float v = 0.f;
        if (k < 64)       v = Wrel [n * 64 + k];
        else if (k < 128) v = Wroot[n * 64 + (k - 64)];
        Bs[i] = to_tf32(v);
    }
    if (tid < 64) bs[tid] = bias[tid];
    if (FINAL && tid < 192) Wl[tid] = Wlin[tid];

    float acc[2][4][4];
    #pragma unroll
    for (int mt = 0; mt < 2; ++mt)
        #pragma unroll
        for (int nt = 0; nt < 4; ++nt)
            #pragma unroll
            for (int r = 0; r < 4; ++r) acc[mt][nt][r] = 0.f;

    #pragma unroll
    for (int ch = 0; ch < 2; ++ch) {
        const float* A = ch ? A1 : A0;
        if (ch) __syncthreads();
        #pragma unroll
        for (int r = 0; r < 8; ++r) {
            int idx = r * 256 + tid;
            int m   = idx >> 4;
            int q   = idx & 15;
            int gm  = m0 + m;
            float4 v = (gm < NN)
                ? *reinterpret_cast<const float4*>(A + (size_t)gm * DH + q * 4)
                : make_float4(0.f, 0.f, 0.f, 0.f);
            v.x = to_tf32(v.x);  v.y = to_tf32(v.y);
            v.z = to_tf32(v.z);  v.w = to_tf32(v.w);
            *reinterpret_cast<float4*>(As + m * AS_STRIDE + q * 4) = v;
        }
        __syncthreads();

        #pragma unroll
        for (int s = 0; s < 8; ++s) {
            unsigned a[2][4], b[4][2];
            int ac = s * 8 + tig;
            #pragma unroll
            for (int mt = 0; mt < 2; ++mt) {
                int r0 = warp_m * 32 + mt * 16 + gid;
                a[mt][0] = __float_as_uint(As[r0 * AS_STRIDE + ac]);
                a[mt][1] = __float_as_uint(As[(r0 + 8) * AS_STRIDE + ac]);
                a[mt][2] = __float_as_uint(As[r0 * AS_STRIDE + ac + 4]);
                a[mt][3] = __float_as_uint(As[(r0 + 8) * AS_STRIDE + ac + 4]);
            }
            int bk = ch * 64 + s * 8 + tig;
            #pragma unroll
            for (int nt = 0; nt < 4; ++nt) {
                int n = warp_n * 32 + nt * 8 + gid;
                b[nt][0] = __float_as_uint(Bs[n * WS_STRIDE + bk]);
                b[nt][1] = __float_as_uint(Bs[n * WS_STRIDE + bk + 4]);
            }
            #pragma unroll
            for (int mt = 0; mt < 2; ++mt)
                #pragma unroll
                for (int nt = 0; nt < 4; ++nt)
                    mma_tf32(acc[mt][nt], a[mt], b[nt]);
        }
    }

    if (!FINAL) {
        #pragma unroll
        for (int mt = 0; mt < 2; ++mt) {
            #pragma unroll
            for (int nt = 0; nt < 4; ++nt) {
                int col = warp_n * 32 + nt * 8 + 2 * tig;
                float b0 = bs[col], b1 = bs[col + 1];
                int r1 = m0 + warp_m * 32 + mt * 16 + gid;
                if (r1 < NN) {
                    float2 o = make_float2(fmaxf(acc[mt][nt][0] + b0, 0.f),
                                           fmaxf(acc[mt][nt][1] + b1, 0.f));
                    *reinterpret_cast<float2*>(out + (size_t)r1 * DH + col) = o;
                }
                int r2 = r1 + 8;
                if (r2 < NN) {
                    float2 o = make_float2(fmaxf(acc[mt][nt][2] + b0, 0.f),
                                           fmaxf(acc[mt][nt][3] + b1, 0.f));
                    *reinterpret_cast<float2*>(out + (size_t)r2 * DH + col) = o;
                }
            }
        }
    } else {
        __syncthreads();
        #pragma unroll
        for (int mt = 0; mt < 2; ++mt) {
            #pragma unroll
            for (int nt = 0; nt < 4; ++nt) {
                int col = warp_n * 32 + nt * 8 + 2 * tig;
                float b0 = bs[col], b1 = bs[col + 1];
                int lr1 = warp_m * 32 + mt * 16 + gid;
                *reinterpret_cast<float2*>(As + lr1 * AS_STRIDE + col) =
                    make_float2(fmaxf(acc[mt][nt][0] + b0, 0.f),
                                fmaxf(acc[mt][nt][1] + b1, 0.f));
                *reinterpret_cast<float2*>(As + (lr1 + 8) * AS_STRIDE + col) =
                    make_float2(fmaxf(acc[mt][nt][2] + b0, 0.f),
                                fmaxf(acc[mt][nt][3] + b1, 0.f));
            }
        }
        __syncthreads();
        #pragma unroll
        for (int r = 0; r < 2; ++r) {
            int idx = tid + 256 * r;
            if (idx < 384) {
                int m = idx / 3;
                int o = idx - 3 * m;
                int gm = m0 + m;
                if (gm < NN) {
                    float s = blin[o];
                    const float* hrow = As + m * AS_STRIDE;
                    const float* wrow = Wl + o * 64;
                    #pragma unroll 16
                    for (int k = 0; k < 64; ++k) s += hrow[k] * wrow[k];
                    out[(size_t)gm * 3 + o] = s;
                }
            }
        }
    }
}

// ---------------- launch ----------------
extern "C" void kernel_launch(void* const* d_in, const int* in_sizes, int n_in,
                              void* d_out, int out_size) {
    const float* x      = (const float*)d_in[0];
    const void*  ei     = d_in[1];
    const float* W1_rel = (const float*)d_in[2];
    const float* b1     = (const float*)d_in[3];
    const float* W1_rt  = (const float*)d_in[4];
    const float* W2_rel = (const float*)d_in[5];
    const float* b2     = (const float*)d_in[6];
    const float* W2_rt  = (const float*)d_in[7];
    const float* W_lin  = (const float*)d_in[8];
    const float* b_lin  = (const float*)d_in[9];
    float*       out    = (float*)d_out;

    float *agg, *h1;
    int *esrc, *rank, *cnt, *offs, *bsum;
    cudaGetSymbolAddress((void**)&agg,  g_agg);
    cudaGetSymbolAddress((void**)&h1,   g_h1);
    cudaGetSymbolAddress((void**)&esrc, g_esrc);
    cudaGetSymbolAddress((void**)&rank, g_rank);
    cudaGetSymbolAddress((void**)&cnt,  g_cnt);
    cudaGetSymbolAddress((void**)&offs, g_offs);
    cudaGetSymbolAddress((void**)&bsum, g_bsum);

    const int smem = (64 * WS_STRIDE + 128 * AS_STRIDE + 64 + 192) * sizeof(float); // 69632 B
    cudaFuncSetAttribute(gemm_tc<false>, cudaFuncAttributeMaxDynamicSharedMemorySize, smem);
    cudaFuncSetAttribute(gemm_tc<true>,  cudaFuncAttributeMaxDynamicSharedMemorySize, smem);

    const int e4grid = (NE / 4 + 255) / 256;
    const int ggrid  = (NN + 127) / 128;
    const int agrid  = (NN + 7) / 8;

    cudaMemsetAsync(cnt, 0, NN * sizeof(int));                          // memset node
    hist_dst<<<e4grid, 256>>>(ei, cnt, rank);                           // 0
    scan_blocks<<<NB, 256>>>(cnt, offs, bsum);                          // 1
    scan_bsums<<<1, 128>>>(bsum, offs);                                 // 2
    place_edges<<<e4grid, 256>>>(ei, rank, offs, bsum, esrc);           // 3 <- ncu

    gather_agg<<<agrid, 256>>>(x, offs, bsum, esrc, (float4*)agg);      // 4
    gemm_tc<false><<<ggrid, 256, smem>>>(agg, x, W1_rel, W1_rt, b1,
                                         nullptr, nullptr, h1);         // 5
    gather_agg<<<agrid, 256>>>(h1, offs, bsum, esrc, (float4*)agg);     // 6
    gemm_tc<true ><<<ggrid, 256, smem>>>(agg, h1, W2_rel, W2_rt, b2,
                                         W_lin, b_lin, out);            // 7
}

// round 17
// speedup vs baseline: 1.2287x; 1.2287x over previous
#include <cuda_runtime.h>
#include <cstdint>

#define NN 100000
#define NE 1600000
#define DH 64
#define SCAN_BLK 1024
#define NB ((NN + SCAN_BLK - 1) / SCAN_BLK) // 98
#define AS_STRIDE 68
#define WS_STRIDE 132

// ---------------- scratch (no allocations allowed) ----------------
__device__ float g_agg[(size_t)NN * DH];
__device__ float g_h1 [(size_t)NN * DH];
__device__ float g_Wn1[64 * WS_STRIDE];   // [n][k] tf32-rounded, k = rel(0:64)|root(64:128)
__device__ float g_Wn2[64 * WS_STRIDE];
__device__ int   g_esrc[NE];              // BYTE offsets of src feature rows (src*256)
__device__ int   g_rank[NE];              // packed (dst << 13) | rank
__device__ int   g_cnt[NN];
__device__ int   g_offs[NN + 1];          // PARTIAL (per-scan-block) exclusive offsets
__device__ int   g_bsum[NB];              // exclusive block sums

__device__ __forceinline__ float to_tf32(float x) {
    unsigned u;
    asm("cvt.rna.tf32.f32 %0, %1;" : "=r"(u) : "f"(x));
    return __uint_as_float(u);
}

__device__ __forceinline__ void mma_tf32(float c[4], const unsigned a[4], const unsigned b[2]) {
    asm("mma.sync.aligned.m16n8k8.row.col.f32.tf32.tf32.f32 "
        "{%0,%1,%2,%3}, {%4,%5,%6,%7}, {%8,%9}, {%0,%1,%2,%3};"
        : "+f"(c[0]), "+f"(c[1]), "+f"(c[2]), "+f"(c[3])
        : "r"(a[0]), "r"(a[1]), "r"(a[2]), "r"(a[3]), "r"(b[0]), "r"(b[1]));
}

// per-block int64-vs-int32 detection (broadcast loads; negligible)
__device__ __forceinline__ int detect_is64_block(const void* ei) {
    __shared__ int s_is64;
    if (threadIdx.x == 0) {
        const long long* p = (const long long*)ei;
        bool all64 = true;
        #pragma unroll
        for (int j = 0; j < 8; ++j) {
            long long v = p[j];
            if (v < 0 || v >= NN) all64 = false;
        }
        s_is64 = all64 ? 1 : 0;
    }
    __syncthreads();
    return s_is64;
}

// ---------------- histogram + packed (dst,rank) per edge (4 edges/thread) -----
__global__ void hist_dst(const void* __restrict__ ei, int* __restrict__ cnt,
                         int* __restrict__ rank) {
    int is64 = detect_is64_block(ei);
    int i = (blockIdx.x * blockDim.x + threadIdx.x) * 4;
    if (i >= NE) return;
    int d0, d1, d2, d3;
    if (is64) {
        longlong4 q = *reinterpret_cast<const longlong4*>((const long long*)ei + NE + i);
        d0 = (int)q.x; d1 = (int)q.y; d2 = (int)q.z; d3 = (int)q.w;
    } else {
        int4 q = *reinterpret_cast<const int4*>((const int*)ei + NE + i);
        d0 = q.x; d1 = q.y; d2 = q.z; d3 = q.w;
    }
    int4 r;
    r.x = (d0 << 13) | atomicAdd(&cnt[d0], 1);
    r.y = (d1 << 13) | atomicAdd(&cnt[d1], 1);
    r.z = (d2 << 13) | atomicAdd(&cnt[d2], 1);
    r.w = (d3 << 13) | atomicAdd(&cnt[d3], 1);
    *reinterpret_cast<int4*>(rank + i) = r;
}

// ---------------- per-block exclusive scan (partial offs) ----------------
__global__ void scan_blocks(const int* __restrict__ cnt,
                            int* __restrict__ offs, int* __restrict__ bsum) {
    __shared__ int sh[256];
    int t = threadIdx.x;
    int base = blockIdx.x * SCAN_BLK + t * 4;
    int c0 = (base + 0 < NN) ? cnt[base + 0] : 0;
    int c1 = (base + 1 < NN) ? cnt[base + 1] : 0;
    int c2 = (base + 2 < NN) ? cnt[base + 2] : 0;
    int c3 = (base + 3 < NN) ? cnt[base + 3] : 0;
    int s = c0 + c1 + c2 + c3;
    sh[t] = s;
    __syncthreads();
    #pragma unroll
    for (int off = 1; off < 256; off <<= 1) {
        int v = (t >= off) ? sh[t - off] : 0;
        __syncthreads();
        sh[t] += v;
        __syncthreads();
    }
    int excl = sh[t] - s;
    if (t == 255) bsum[blockIdx.x] = sh[255];
    if (base + 0 < NN) offs[base + 0] = excl;  excl += c0;
    if (base + 1 < NN) offs[base + 1] = excl;  excl += c1;
    if (base + 2 < NN) offs[base + 2] = excl;  excl += c2;
    if (base + 3 < NN) offs[base + 3] = excl;
}

__global__ void scan_bsums(int* __restrict__ bsum, int* __restrict__ offs) {
    __shared__ int sh[128];
    int t = threadIdx.x;
    int v = (t < NB) ? bsum[t] : 0;
    sh[t] = v;
    __syncthreads();
    #pragma unroll
    for (int off = 1; off < 128; off <<= 1) {
        int u = (t >= off) ? sh[t - off] : 0;
        __syncthreads();
        sh[t] += u;
        __syncthreads();
    }
    if (t < NB) bsum[t] = sh[t] - v;           // exclusive
    if (t == NB - 1) offs[NN] = v;             // partial: offs[NN]+bsum[NB-1] = NE
}

// ---------------- place edges, NO atomics, dst from packed rank ----------------
__global__ void place_edges(const void* __restrict__ ei,
                            const int* __restrict__ rank,
                            const int* __restrict__ offs,
                            const int* __restrict__ bsum,
                            int* __restrict__ esrc) {
    int is64 = detect_is64_block(ei);
    int i = (blockIdx.x * blockDim.x + threadIdx.x) * 4;
    if (i >= NE) return;
    int s0, s1, s2, s3;
    if (is64) {
        const long long* p = (const long long*)ei;
        longlong4 qs = *reinterpret_cast<const longlong4*>(p + i);
        s0 = (int)qs.x; s1 = (int)qs.y; s2 = (int)qs.z; s3 = (int)qs.w;
    } else {
        const int* p = (const int*)ei;
        int4 qs = *reinterpret_cast<const int4*>(p + i);
        s0 = qs.x; s1 = qs.y; s2 = qs.z; s3 = qs.w;
    }
    int4 rq = *reinterpret_cast<const int4*>(rank + i);
    int d0 = rq.x >> 13, r0 = rq.x & 8191;
    int d1 = rq.y >> 13, r1 = rq.y & 8191;
    int d2 = rq.z >> 13, r2 = rq.z & 8191;
    int d3 = rq.w >> 13, r3 = rq.w & 8191;
    esrc[offs[d0] + bsum[d0 >> 10] + r0] = s0 << 8;   // byte offsets (row = 256B)
    esrc[offs[d1] + bsum[d1 >> 10] + r1] = s1 << 8;
    esrc[offs[d2] + bsum[d2 >> 10] + r2] = s2 << 8;
    esrc[offs[d3] + bsum[d3 >> 10] + r3] = s3 << 8;
}

// ---------------- both weight tensors -> tf32 [n][k] ----------------
__global__ void prep_w2(const float* __restrict__ W1rel, const float* __restrict__ W1rt,
                        const float* __restrict__ W2rel, const float* __restrict__ W2rt,
                        float* __restrict__ Wn1, float* __restrict__ Wn2) {
    int i = blockIdx.x * blockDim.x + threadIdx.x;
    int layer = (i >= 64 * WS_STRIDE);
    int j = i - layer * 64 * WS_STRIDE;
    if (j < 64 * WS_STRIDE && i < 2 * 64 * WS_STRIDE) {
        int n = j / WS_STRIDE;
        int k = j - n * WS_STRIDE;
        const float* Wrel = layer ? W2rel : W1rel;
        const float* Wrt  = layer ? W2rt  : W1rt;
        float v = 0.f;
        if (k < 64)       v = Wrel[n * 64 + k];
        else if (k < 128) v = Wrt [n * 64 + (k - 64)];
        (layer ? Wn2 : Wn1)[j] = to_tf32(v);
    }
}

// ---------------- gather: float4/lane, byte offsets, esrc-prefetch ----------
__global__ void __launch_bounds__(256)
gather_agg(const float* __restrict__ feat,    // rows of 256B
           const int* __restrict__ offs,      // partial
           const int* __restrict__ bsum,
           const int* __restrict__ esrc,      // byte offsets
           float4* __restrict__ agg) {        // [NN*16]
    int node = blockIdx.x * (blockDim.x >> 5) + (threadIdx.x >> 5);
    if (node >= NN) return;
    int lane = threadIdx.x & 31;
    int half = lane >> 4;
    int sub  = lane & 15;
    int s0 = offs[node]     + bsum[node >> 10];
    int s1 = offs[node + 1] + bsum[(node + 1) >> 10];
    const char* fb = reinterpret_cast<const char*>(feat) + sub * 16;
    float ax = 0.f, ay = 0.f, az = 0.f, aw = 0.f;
    int j = s0;

    if (j + 8 <= s1) {
        int e0 = esrc[j + half];
        int e1 = esrc[j + 2 + half];
        int e2 = esrc[j + 4 + half];
        int e3 = esrc[j + 6 + half];
        for (;;) {
            bool more = (j + 16 <= s1);
            int n0, n1, n2, n3;
            if (more) {
                n0 = esrc[j + 8 + half];
                n1 = esrc[j + 10 + half];
                n2 = esrc[j + 12 + half];
                n3 = esrc[j + 14 + half];
            }
            float4 v0 = *reinterpret_cast<const float4*>(fb + e0);
            float4 v1 = *reinterpret_cast<const float4*>(fb + e1);
            float4 v2 = *reinterpret_cast<const float4*>(fb + e2);
            float4 v3 = *reinterpret_cast<const float4*>(fb + e3);
            ax += (v0.x + v1.x) + (v2.x + v3.x);
            ay += (v0.y + v1.y) + (v2.y + v3.y);
            az += (v0.z + v1.z) + (v2.z + v3.z);
            aw += (v0.w + v1.w) + (v2.w + v3.w);
            j += 8;
            if (!more) break;
            e0 = n0; e1 = n1; e2 = n2; e3 = n3;
        }
    }
    for (; j + 4 <= s1; j += 4) {
        int e0 = esrc[j + half];
        int e1 = esrc[j + 2 + half];
        float4 v0 = *reinterpret_cast<const float4*>(fb + e0);
        float4 v1 = *reinterpret_cast<const float4*>(fb + e1);
        ax += v0.x + v1.x;  ay += v0.y + v1.y;
        az += v0.z + v1.z;  aw += v0.w + v1.w;
    }
    for (; j + 2 <= s1; j += 2) {
        int e = esrc[j + half];
        float4 v = *reinterpret_cast<const float4*>(fb + e);
        ax += v.x;  ay += v.y;  az += v.z;  aw += v.w;
    }
    if (j < s1 && half == 0) {
        float4 v = *reinterpret_cast<const float4*>(fb + esrc[j]);
        ax += v.x;  ay += v.y;  az += v.z;  aw += v.w;
    }
    ax += __shfl_xor_sync(0xffffffffu, ax, 16);
    ay += __shfl_xor_sync(0xffffffffu, ay, 16);
    az += __shfl_xor_sync(0xffffffffu, az, 16);
    aw += __shfl_xor_sync(0xffffffffu, aw, 16);
    if (half == 0) agg[(size_t)node * 16 + sub] = make_float4(ax, ay, az, aw);
}

// ---------------- tf32 tensor-core dual-GEMM (+ fused head on FINAL) ----------
template<bool FINAL>
__global__ void __launch_bounds__(256)
gemm_tc(const float* __restrict__ A0,    // agg [NN,64]
        const float* __restrict__ A1,    // xin [NN,64]
        const float* __restrict__ Wn,    // [64][WS_STRIDE] tf32
        const float* __restrict__ bias,  // [64]
        const float* __restrict__ Wlin,  // [3,64]  (FINAL)
        const float* __restrict__ blin,  // [3]     (FINAL)
        float* __restrict__ out) {       // [NN,64] or [NN,3]
    extern __shared__ float sm[];
    float* Bs = sm;                         // [64][132]
    float* As = Bs + 64 * WS_STRIDE;        // [128][68]
    float* bs = As + 128 * AS_STRIDE;       // [64]
    float* Wl = bs + 64;                    // [192]

    const int tid    = threadIdx.x;
    const int lane   = tid & 31;
    const int warp   = tid >> 5;
    const int warp_m = warp & 3;
    const int warp_n = warp >> 2;
    const int gid    = lane >> 2;
    const int tig    = lane & 3;
    const int m0     = blockIdx.x * 128;

    for (int i = tid; i < 64 * WS_STRIDE; i += 256) Bs[i] = Wn[i];
    if (tid < 64) bs[tid] = bias[tid];
    if (FINAL && tid < 192) Wl[tid] = Wlin[tid];

    float acc[2][4][4];
    #pragma unroll
    for (int mt = 0; mt < 2; ++mt)
        #pragma unroll
        for (int nt = 0; nt < 4; ++nt)
            #pragma unroll
            for (int r = 0; r < 4; ++r) acc[mt][nt][r] = 0.f;

    #pragma unroll
    for (int ch = 0; ch < 2; ++ch) {
        const float* A = ch ? A1 : A0;
        if (ch) __syncthreads();
        #pragma unroll
        for (int r = 0; r < 8; ++r) {
            int idx = r * 256 + tid;
            int m   = idx >> 4;
            int q   = idx & 15;
            int gm  = m0 + m;
            float4 v = (gm < NN)
                ? *reinterpret_cast<const float4*>(A + (size_t)gm * DH + q * 4)
                : make_float4(0.f, 0.f, 0.f, 0.f);
            v.x = to_tf32(v.x);  v.y = to_tf32(v.y);
            v.z = to_tf32(v.z);  v.w = to_tf32(v.w);
            *reinterpret_cast<float4*>(As + m * AS_STRIDE + q * 4) = v;
        }
        __syncthreads();

        #pragma unroll
        for (int s = 0; s < 8; ++s) {
            unsigned a[2][4], b[4][2];
            int ac = s * 8 + tig;
            #pragma unroll
            for (int mt = 0; mt < 2; ++mt) {
                int r0 = warp_m * 32 + mt * 16 + gid;
                a[mt][0] = __float_as_uint(As[r0 * AS_STRIDE + ac]);
                a[mt][1] = __float_as_uint(As[(r0 + 8) * AS_STRIDE + ac]);
                a[mt][2] = __float_as_uint(As[r0 * AS_STRIDE + ac + 4]);
                a[mt][3] = __float_as_uint(As[(r0 + 8) * AS_STRIDE + ac + 4]);
            }
            int bk = ch * 64 + s * 8 + tig;
            #pragma unroll
            for (int nt = 0; nt < 4; ++nt) {
                int n = warp_n * 32 + nt * 8 + gid;
                b[nt][0] = __float_as_uint(Bs[n * WS_STRIDE + bk]);
                b[nt][1] = __float_as_uint(Bs[n * WS_STRIDE + bk + 4]);
            }
            #pragma unroll
            for (int mt = 0; mt < 2; ++mt)
                #pragma unroll
                for (int nt = 0; nt < 4; ++nt)
                    mma_tf32(acc[mt][nt], a[mt], b[nt]);
        }
    }

    if (!FINAL) {
        #pragma unroll
        for (int mt = 0; mt < 2; ++mt) {
            #pragma unroll
            for (int nt = 0; nt < 4; ++nt) {
                int col = warp_n * 32 + nt * 8 + 2 * tig;
                float b0 = bs[col], b1 = bs[col + 1];
                int r1 = m0 + warp_m * 32 + mt * 16 + gid;
                if (r1 < NN) {
                    float2 o = make_float2(fmaxf(acc[mt][nt][0] + b0, 0.f),
                                           fmaxf(acc[mt][nt][1] + b1, 0.f));
                    *reinterpret_cast<float2*>(out + (size_t)r1 * DH + col) = o;
                }
                int r2 = r1 + 8;
                if (r2 < NN) {
                    float2 o = make_float2(fmaxf(acc[mt][nt][2] + b0, 0.f),
                                           fmaxf(acc[mt][nt][3] + b1, 0.f));
                    *reinterpret_cast<float2*>(out + (size_t)r2 * DH + col) = o;
                }
            }
        }
    } else {
        __syncthreads();
        #pragma unroll
        for (int mt = 0; mt < 2; ++mt) {
            #pragma unroll
            for (int nt = 0; nt < 4; ++nt) {
                int col = warp_n * 32 + nt * 8 + 2 * tig;
                float b0 = bs[col], b1 = bs[col + 1];
                int lr1 = warp_m * 32 + mt * 16 + gid;
                *reinterpret_cast<float2*>(As + lr1 * AS_STRIDE + col) =
                    make_float2(fmaxf(acc[mt][nt][0] + b0, 0.f),
                                fmaxf(acc[mt][nt][1] + b1, 0.f));
                *reinterpret_cast<float2*>(As + (lr1 + 8) * AS_STRIDE + col) =
                    make_float2(fmaxf(acc[mt][nt][2] + b0, 0.f),
                                fmaxf(acc[mt][nt][3] + b1, 0.f));
            }
        }
        __syncthreads();
        #pragma unroll
        for (int r = 0; r < 2; ++r) {
            int idx = tid + 256 * r;
            if (idx < 384) {
                int m = idx / 3;
                int o = idx - 3 * m;
                int gm = m0 + m;
                if (gm < NN) {
                    float s = blin[o];
                    const float* hrow = As + m * AS_STRIDE;
                    const float* wrow = Wl + o * 64;
                    #pragma unroll 16
                    for (int k = 0; k < 64; ++k) s += hrow[k] * wrow[k];
                    out[(size_t)gm * 3 + o] = s;
                }
            }
        }
    }
}

// ---------------- launch ----------------
extern "C" void kernel_launch(void* const* d_in, const int* in_sizes, int n_in,
                              void* d_out, int out_size) {
    const float* x      = (const float*)d_in[0];
    const void*  ei     = d_in[1];
    const float* W1_rel = (const float*)d_in[2];
    const float* b1     = (const float*)d_in[3];
    const float* W1_rt  = (const float*)d_in[4];
    const float* W2_rel = (const float*)d_in[5];
    const float* b2     = (const float*)d_in[6];
    const float* W2_rt  = (const float*)d_in[7];
    const float* W_lin  = (const float*)d_in[8];
    const float* b_lin  = (const float*)d_in[9];
    float*       out    = (float*)d_out;

    float *agg, *h1, *Wn1, *Wn2;
    int *esrc, *rank, *cnt, *offs, *bsum;
    cudaGetSymbolAddress((void**)&agg,  g_agg);
    cudaGetSymbolAddress((void**)&h1,   g_h1);
    cudaGetSymbolAddress((void**)&Wn1,  g_Wn1);
    cudaGetSymbolAddress((void**)&Wn2,  g_Wn2);
    cudaGetSymbolAddress((void**)&esrc, g_esrc);
    cudaGetSymbolAddress((void**)&rank, g_rank);
    cudaGetSymbolAddress((void**)&cnt,  g_cnt);
    cudaGetSymbolAddress((void**)&offs, g_offs);
    cudaGetSymbolAddress((void**)&bsum, g_bsum);

    const int smem = (64 * WS_STRIDE + 128 * AS_STRIDE + 64 + 192) * sizeof(float); // 69632 B
    cudaFuncSetAttribute(gemm_tc<false>, cudaFuncAttributeMaxDynamicSharedMemorySize, smem);
    cudaFuncSetAttribute(gemm_tc<true>,  cudaFuncAttributeMaxDynamicSharedMemorySize, smem);

    const int e4grid = (NE / 4 + 255) / 256;
    const int ggrid  = (NN + 127) / 128;
    const int agrid  = (NN + 7) / 8;
    const int wgrid  = (2 * 64 * WS_STRIDE + 255) / 256;

    cudaMemsetAsync(cnt, 0, NN * sizeof(int));                          // memset node
    hist_dst<<<e4grid, 256>>>(ei, cnt, rank);                           // 0
    scan_blocks<<<NB, 256>>>(cnt, offs, bsum);                          // 1
    scan_bsums<<<1, 128>>>(bsum, offs);                                 // 2
    place_edges<<<e4grid, 256>>>(ei, rank, offs, bsum, esrc);           // 3 <- ncu
    prep_w2<<<wgrid, 256>>>(W1_rel, W1_rt, W2_rel, W2_rt, Wn1, Wn2);    // 4

    gather_agg<<<agrid, 256>>>(x, offs, bsum, esrc, (float4*)agg);      // 5
    gemm_tc<false><<<ggrid, 256, smem>>>(agg, x, Wn1, b1, nullptr, nullptr, h1);  // 6
    gather_agg<<<agrid, 256>>>(h1, offs, bsum, esrc, (float4*)agg);     // 7
    gemm_tc<true ><<<ggrid, 256, smem>>>(agg, h1, Wn2, b2, W_lin, b_lin, out);    // 8
}